// round 3
// baseline (speedup 1.0000x reference)
#include <cuda_runtime.h>
#include <math.h>

#define NB 4
#define ND 1024
#define NS 2048
#define NH 16
#define NHD 64
#define NTOK (NB*NS)   // 8192
#define PADS 68        // smem row stride (floats); 68*4=272B, 16B-aligned

// Scratch (allocation-free rule: device globals)
__device__ float g_xt[(size_t)NTOK * ND];
__device__ float g_q [(size_t)NTOK * ND];
__device__ float g_k [(size_t)NTOK * ND];
__device__ float g_v [(size_t)NTOK * ND];
__device__ float g_att[(size_t)NTOK * ND];

// ---------------------------------------------------------------------------
// Kernel 1: x[b,d,s] + PE(d,s)  ->  g_xt[(b*S+s)*D + d]   (transpose via smem)
// ---------------------------------------------------------------------------
__global__ void pe_transpose_kernel(const float* __restrict__ x) {
    __shared__ float tile[32][33];
    int b  = blockIdx.z;
    int d0 = blockIdx.y * 32;
    int s0 = blockIdx.x * 32;
    int tx = threadIdx.x, ty = threadIdx.y;
    #pragma unroll
    for (int i = 0; i < 32; i += 8) {
        int d = d0 + ty + i;
        int s = s0 + tx;
        float v = x[(size_t)b * ND * NS + (size_t)d * NS + s];
        float base = (float)(d & ~1);
        float freq = __expf(base * (-9.210340371976184f / (float)ND)); // -ln(10000)/D
        float ang  = (float)s * freq;
        v += (d & 1) ? cosf(ang) : sinf(ang);
        tile[ty + i][tx] = v;
    }
    __syncthreads();
    #pragma unroll
    for (int i = 0; i < 32; i += 8) {
        int s = s0 + ty + i;
        int d = d0 + tx;
        g_xt[((size_t)b * NS + s) * ND + d] = tile[tx][ty + i];
    }
}

// ---------------------------------------------------------------------------
// Kernel 2: C[M,N] = A[M,K] * W[N,K]^T + bias   (M=8192, N=K=1024)
// 128x128 tile, BK=8, 256 threads, 8x8 per thread arranged as 4 quads of 4x4.
// TOUT=1: write transposed to out[b, n, s] (final [B,D,S] layout).
// ---------------------------------------------------------------------------
template<int TOUT>
__global__ void __launch_bounds__(256) sgemm_bias_kernel(
    const float* __restrict__ A, const float* __restrict__ W,
    const float* __restrict__ bias, float* __restrict__ C)
{
    const int K = ND;
    __shared__ float As[8][128];
    __shared__ float Ws[8][128];
    int tid  = threadIdx.x;
    int row0 = blockIdx.y * 128;
    int col0 = blockIdx.x * 128;
    int lr = tid >> 1;            // 0..127 (tile row for loads)
    int lc = (tid & 1) * 4;       // 0 or 4 (k offset for loads)
    const float* Ap = A + (size_t)(row0 + lr) * K + lc;
    const float* Wp = W + (size_t)(col0 + lr) * K + lc;
    int tx = tid & 15, ty = tid >> 4;

    float acc[8][8];
    #pragma unroll
    for (int i = 0; i < 8; i++)
        #pragma unroll
        for (int j = 0; j < 8; j++) acc[i][j] = 0.f;

    for (int k0 = 0; k0 < K; k0 += 8) {
        float4 av = *(const float4*)(Ap + k0);
        float4 wv = *(const float4*)(Wp + k0);
        As[lc+0][lr] = av.x; As[lc+1][lr] = av.y; As[lc+2][lr] = av.z; As[lc+3][lr] = av.w;
        Ws[lc+0][lr] = wv.x; Ws[lc+1][lr] = wv.y; Ws[lc+2][lr] = wv.z; Ws[lc+3][lr] = wv.w;
        __syncthreads();
        #pragma unroll
        for (int kk = 0; kk < 8; kk++) {
            float4 a0 = *(const float4*)&As[kk][ty*4];
            float4 a1 = *(const float4*)&As[kk][ty*4 + 64];
            float4 w0 = *(const float4*)&Ws[kk][tx*4];
            float4 w1 = *(const float4*)&Ws[kk][tx*4 + 64];
            float a[8] = {a0.x,a0.y,a0.z,a0.w,a1.x,a1.y,a1.z,a1.w};
            float w[8] = {w0.x,w0.y,w0.z,w0.w,w1.x,w1.y,w1.z,w1.w};
            #pragma unroll
            for (int i = 0; i < 8; i++)
                #pragma unroll
                for (int j = 0; j < 8; j++)
                    acc[i][j] += a[i] * w[j];
        }
        __syncthreads();
    }

    #pragma unroll
    for (int i = 0; i < 8; i++) {
        int r = row0 + ((i < 4) ? (ty*4 + i) : (64 + ty*4 + i - 4));
        #pragma unroll
        for (int j = 0; j < 8; j++) {
            int c = col0 + ((j < 4) ? (tx*4 + j) : (64 + tx*4 + j - 4));
            float v = acc[i][j] + __ldg(&bias[c]);
            if (TOUT) {
                int bb = r >> 11;          // /NS
                int s  = r & (NS - 1);
                C[((size_t)bb * ND + c) * NS + s] = v;
            } else {
                C[(size_t)r * ND + c] = v;
            }
        }
    }
}

// ---------------------------------------------------------------------------
// Kernel 3: flash attention, fp32. Block = (64 q-rows) x one (b,h).
// 256 threads: thread (r = tid/4, g = tid%4) owns 16 score cols / 16 out dims.
// ---------------------------------------------------------------------------
__global__ void __launch_bounds__(256) flash_attn_kernel() {
    extern __shared__ float sm[];
    float* Qs = sm;                 // [64][PADS]  q rows (pre-scaled)
    float* Kt = Qs + 64 * PADS;     // [64][PADS]  K transposed: Kt[d][c]
    float* Vs = Kt + 64 * PADS;     // [64][PADS]  V rows
    float* Ps = Vs + 64 * PADS;     // [64][PADS]  probs

    int b  = blockIdx.z, h = blockIdx.y;
    int q0 = blockIdx.x * 64;
    int tid = threadIdx.x;
    int r = tid >> 2;               // 0..63
    int g = tid & 3;                // 0..3
    int lr2 = tid >> 4;             // loader: 16 rows x 16 lanes
    int lc2 = (tid & 15) * 4;
    const float scale = 0.125f;     // 1/sqrt(64)
    size_t head_off = (size_t)h * NHD;

    #pragma unroll
    for (int st = 0; st < 4; st++) {
        int row = lr2 + st * 16;
        float4 v = *(const float4*)(g_q + ((size_t)(b*NS + q0 + row)) * ND + head_off + lc2);
        v.x *= scale; v.y *= scale; v.z *= scale; v.w *= scale;
        *(float4*)&Qs[row * PADS + lc2] = v;
    }

    float m_run = -1e30f, l_run = 0.f;
    float acc[16];
    #pragma unroll
    for (int i = 0; i < 16; i++) acc[i] = 0.f;

    for (int kt0 = 0; kt0 < NS; kt0 += 64) {
        #pragma unroll
        for (int st = 0; st < 4; st++) {
            int row = lr2 + st * 16;
            size_t tok = (size_t)(b*NS + kt0 + row) * ND + head_off + lc2;
            float4 kv = *(const float4*)(g_k + tok);
            Kt[(lc2+0)*PADS + row] = kv.x;
            Kt[(lc2+1)*PADS + row] = kv.y;
            Kt[(lc2+2)*PADS + row] = kv.z;
            Kt[(lc2+3)*PADS + row] = kv.w;
            float4 vv = *(const float4*)(g_v + tok);
            *(float4*)&Vs[row * PADS + lc2] = vv;
        }
        __syncthreads();

        // S = Q K^T : thread covers cols c = g*4 + qq*16 + i
        float sv[16];
        #pragma unroll
        for (int i = 0; i < 16; i++) sv[i] = 0.f;
        #pragma unroll 4
        for (int d = 0; d < 64; d++) {
            float qv = Qs[r * PADS + d];
            const float* krow = &Kt[d * PADS + g*4];
            #pragma unroll
            for (int qq = 0; qq < 4; qq++) {
                float4 kv = *(const float4*)(krow + qq * 16);
                sv[qq*4+0] += qv * kv.x;
                sv[qq*4+1] += qv * kv.y;
                sv[qq*4+2] += qv * kv.z;
                sv[qq*4+3] += qv * kv.w;
            }
        }

        // online softmax (4 lanes per row)
        float mt = sv[0];
        #pragma unroll
        for (int i = 1; i < 16; i++) mt = fmaxf(mt, sv[i]);
        mt = fmaxf(mt, __shfl_xor_sync(0xffffffffu, mt, 1));
        mt = fmaxf(mt, __shfl_xor_sync(0xffffffffu, mt, 2));
        float m_new = fmaxf(m_run, mt);
        float corr  = __expf(m_run - m_new);
        float lsum = 0.f;
        #pragma unroll
        for (int i = 0; i < 16; i++) { sv[i] = __expf(sv[i] - m_new); lsum += sv[i]; }
        lsum += __shfl_xor_sync(0xffffffffu, lsum, 1);
        lsum += __shfl_xor_sync(0xffffffffu, lsum, 2);
        l_run = l_run * corr + lsum;
        m_run = m_new;
        #pragma unroll
        for (int i = 0; i < 16; i++) acc[i] *= corr;

        #pragma unroll
        for (int qq = 0; qq < 4; qq++) {
            float4 pv = make_float4(sv[qq*4+0], sv[qq*4+1], sv[qq*4+2], sv[qq*4+3]);
            *(float4*)&Ps[r * PADS + g*4 + qq*16] = pv;
        }
        __syncthreads();

        // O += P V : thread owns out dims d = g*16 + qq*4 + i
        #pragma unroll 4
        for (int c = 0; c < 64; c++) {
            float pv = Ps[r * PADS + c];
            const float* vrow = &Vs[c * PADS + g*16];
            #pragma unroll
            for (int qq = 0; qq < 4; qq++) {
                float4 vv = *(const float4*)(vrow + qq * 4);
                acc[qq*4+0] += pv * vv.x;
                acc[qq*4+1] += pv * vv.y;
                acc[qq*4+2] += pv * vv.z;
                acc[qq*4+3] += pv * vv.w;
            }
        }
        __syncthreads();
    }

    float inv_l = 1.f / l_run;
    float* ob = g_att + ((size_t)(b*NS + q0 + r)) * ND + head_off + g*16;
    #pragma unroll
    for (int qq = 0; qq < 4; qq++) {
        float4 ov = make_float4(acc[qq*4+0]*inv_l, acc[qq*4+1]*inv_l,
                                acc[qq*4+2]*inv_l, acc[qq*4+3]*inv_l);
        *(float4*)(ob + qq*4) = ov;
    }
}

// ---------------------------------------------------------------------------
extern "C" void kernel_launch(void* const* d_in, const int* in_sizes, int n_in,
                              void* d_out, int out_size) {
    const float* x  = (const float*)d_in[0];
    const float* Wq = (const float*)d_in[1];
    const float* bq = (const float*)d_in[2];
    const float* Wk = (const float*)d_in[3];
    const float* bk = (const float*)d_in[4];
    const float* Wv = (const float*)d_in[5];
    const float* bv = (const float*)d_in[6];
    const float* Wo = (const float*)d_in[7];
    const float* bo = (const float*)d_in[8];
    float* out = (float*)d_out;

    float *xt, *q, *k, *v, *att;
    cudaGetSymbolAddress((void**)&xt,  g_xt);
    cudaGetSymbolAddress((void**)&q,   g_q);
    cudaGetSymbolAddress((void**)&k,   g_k);
    cudaGetSymbolAddress((void**)&v,   g_v);
    cudaGetSymbolAddress((void**)&att, g_att);

    dim3 pegrid(NS/32, ND/32, NB);
    pe_transpose_kernel<<<pegrid, dim3(32, 8)>>>(x);

    dim3 ggrid(ND/128, NTOK/128);
    sgemm_bias_kernel<0><<<ggrid, 256>>>(xt, Wq, bq, q);
    sgemm_bias_kernel<0><<<ggrid, 256>>>(xt, Wk, bk, k);
    sgemm_bias_kernel<0><<<ggrid, 256>>>(xt, Wv, bv, v);

    int attn_smem = 4 * 64 * PADS * (int)sizeof(float);  // 69632 B
    cudaFuncSetAttribute(flash_attn_kernel,
                         cudaFuncAttributeMaxDynamicSharedMemorySize, attn_smem);
    flash_attn_kernel<<<dim3(NS/64, NH, NB), 256, attn_smem>>>();

    sgemm_bias_kernel<1><<<ggrid, 256>>>(att, Wo, bo, out);
}

// round 4
// speedup vs baseline: 2.5524x; 2.5524x over previous
#include <cuda_runtime.h>
#include <math.h>

#define NB 4
#define ND 1024
#define NS 2048
#define NH 16
#define NTOK (NB*NS)   // 8192

// Scratch (allocation-free rule: device globals)
__device__ float g_xt[(size_t)NTOK * ND];
__device__ float g_q [(size_t)NTOK * ND];
__device__ float g_k [(size_t)NTOK * ND];
__device__ float g_v [(size_t)NTOK * ND];
__device__ float g_att[(size_t)NTOK * ND];

// ---------------------------------------------------------------------------
// Kernel 1: x[b,d,s] + PE(d,s)  ->  g_xt[(b*S+s)*D + d]   (transpose via smem)
// ---------------------------------------------------------------------------
__global__ void pe_transpose_kernel(const float* __restrict__ x) {
    __shared__ float tile[32][33];
    int b  = blockIdx.z;
    int d0 = blockIdx.y * 32;
    int s0 = blockIdx.x * 32;
    int tx = threadIdx.x, ty = threadIdx.y;
    #pragma unroll
    for (int i = 0; i < 32; i += 8) {
        int d = d0 + ty + i;
        int s = s0 + tx;
        float v = x[(size_t)b * ND * NS + (size_t)d * NS + s];
        float base = (float)(d & ~1);
        float freq = __expf(base * (-9.210340371976184f / (float)ND)); // -ln(10000)/D
        float ang  = (float)s * freq;
        v += (d & 1) ? cosf(ang) : sinf(ang);
        tile[ty + i][tx] = v;
    }
    __syncthreads();
    #pragma unroll
    for (int i = 0; i < 32; i += 8) {
        int s = s0 + ty + i;
        int d = d0 + tx;
        g_xt[((size_t)b * NS + s) * ND + d] = tile[tx][ty + i];
    }
}

// ---------------------------------------------------------------------------
// Kernel 2: C[M,N] = A[M,K] * W[N,K]^T + bias   (M=8192, N=K=1024)
// 128x128 tile, BK=8, 256 threads, 8x8 per thread, DOUBLE-BUFFERED smem.
// TOUT=1: write transposed to out[b, n, s] (final [B,D,S] layout).
// ---------------------------------------------------------------------------
template<int TOUT>
__global__ void __launch_bounds__(256, 2) sgemm_bias_kernel(
    const float* __restrict__ A, const float* __restrict__ W,
    const float* __restrict__ bias, float* __restrict__ C)
{
    const int K = ND;
    __shared__ float As[2][8][128];
    __shared__ float Ws[2][8][128];
    int tid  = threadIdx.x;
    int row0 = blockIdx.y * 128;
    int col0 = blockIdx.x * 128;
    int lr = tid >> 1;            // 0..127 (tile row for loads)
    int lc = (tid & 1) * 4;       // 0 or 4 (k offset for loads)
    const float* Ap = A + (size_t)(row0 + lr) * K + lc;
    const float* Wp = W + (size_t)(col0 + lr) * K + lc;
    int tx = tid & 15, ty = tid >> 4;

    float acc[8][8];
    #pragma unroll
    for (int i = 0; i < 8; i++)
        #pragma unroll
        for (int j = 0; j < 8; j++) acc[i][j] = 0.f;

    // prologue: load first k-slice into buffer 0
    {
        float4 av = *(const float4*)Ap;
        float4 wv = *(const float4*)Wp;
        As[0][lc+0][lr] = av.x; As[0][lc+1][lr] = av.y;
        As[0][lc+2][lr] = av.z; As[0][lc+3][lr] = av.w;
        Ws[0][lc+0][lr] = wv.x; Ws[0][lc+1][lr] = wv.y;
        Ws[0][lc+2][lr] = wv.z; Ws[0][lc+3][lr] = wv.w;
    }
    __syncthreads();

    int buf = 0;
    for (int k0 = 8; k0 <= K; k0 += 8) {
        float4 av2, wv2;
        bool more = (k0 < K);
        if (more) {
            av2 = *(const float4*)(Ap + k0);
            wv2 = *(const float4*)(Wp + k0);
        }
        #pragma unroll
        for (int kk = 0; kk < 8; kk++) {
            float4 a0 = *(const float4*)&As[buf][kk][ty*4];
            float4 a1 = *(const float4*)&As[buf][kk][ty*4 + 64];
            float4 w0 = *(const float4*)&Ws[buf][kk][tx*4];
            float4 w1 = *(const float4*)&Ws[buf][kk][tx*4 + 64];
            float a[8] = {a0.x,a0.y,a0.z,a0.w,a1.x,a1.y,a1.z,a1.w};
            float w[8] = {w0.x,w0.y,w0.z,w0.w,w1.x,w1.y,w1.z,w1.w};
            #pragma unroll
            for (int i = 0; i < 8; i++)
                #pragma unroll
                for (int j = 0; j < 8; j++)
                    acc[i][j] += a[i] * w[j];
        }
        if (more) {
            int b2 = buf ^ 1;
            As[b2][lc+0][lr] = av2.x; As[b2][lc+1][lr] = av2.y;
            As[b2][lc+2][lr] = av2.z; As[b2][lc+3][lr] = av2.w;
            Ws[b2][lc+0][lr] = wv2.x; Ws[b2][lc+1][lr] = wv2.y;
            Ws[b2][lc+2][lr] = wv2.z; Ws[b2][lc+3][lr] = wv2.w;
            __syncthreads();
        }
        buf ^= 1;
    }

    if (TOUT) {
        // out[(b*ND + c)*NS + s], s along i (contiguous quads)
        int bb = row0 >> 11;
        int s0 = row0 & (NS - 1);
        #pragma unroll
        for (int j = 0; j < 8; j++) {
            int c = col0 + ((j < 4) ? (tx*4 + j) : (64 + tx*4 + j - 4));
            float bv = __ldg(&bias[c]);
            float* cb = C + ((size_t)bb * ND + c) * NS + s0 + ty*4;
            float4 lo = make_float4(acc[0][j]+bv, acc[1][j]+bv, acc[2][j]+bv, acc[3][j]+bv);
            float4 hi = make_float4(acc[4][j]+bv, acc[5][j]+bv, acc[6][j]+bv, acc[7][j]+bv);
            *(float4*)(cb)      = lo;
            *(float4*)(cb + 64) = hi;
        }
    } else {
        float4 bv0 = *(const float4*)&bias[col0 + tx*4];
        float4 bv1 = *(const float4*)&bias[col0 + tx*4 + 64];
        #pragma unroll
        for (int i = 0; i < 8; i++) {
            int r = row0 + ((i < 4) ? (ty*4 + i) : (64 + ty*4 + i - 4));
            float* cb = C + (size_t)r * ND + col0 + tx*4;
            float4 lo = make_float4(acc[i][0]+bv0.x, acc[i][1]+bv0.y,
                                    acc[i][2]+bv0.z, acc[i][3]+bv0.w);
            float4 hi = make_float4(acc[i][4]+bv1.x, acc[i][5]+bv1.y,
                                    acc[i][6]+bv1.z, acc[i][7]+bv1.w);
            *(float4*)(cb)      = lo;
            *(float4*)(cb + 64) = hi;
        }
    }
}

// ---------------------------------------------------------------------------
// Kernel 3: flash attention v2, fp32, GEMM-style register blocking.
// Block = 128 q-rows x one (b,h), 256 threads, k-tiles of 64.
// Thread map (both GEMMs): ty = tid&15 (fast, 16 lanes = shfl group),
//                          tx = tid>>4.
// Score phase computes S^T[c][r] = (K*scale... Q pre-scaled) so softmax
// reduction over c is a 16-lane shfl butterfly over ty.
// P stored col-major with XOR-swizzled float4 slots (conflict-free).
// PV phase computes O^T[d][r] with V row-major as the A-operand.
// smem layouts: Qs[64][132] (d-major), Ks[64][68] (d-major),
//               Vs[64][68] (row-major), Ps[64][128] (c-major, swizzled).
// ---------------------------------------------------------------------------
#define QS_STR 132
#define KS_STR 68

__global__ void __launch_bounds__(256, 2) flash_attn_kernel() {
    extern __shared__ float sm[];
    float* Qs = sm;                     // [64][132]  Q^T (d-major), pre-scaled
    float* Ks = Qs + 64 * QS_STR;       // [64][68]   K^T (d-major)
    float* Vs = Ks + 64 * KS_STR;       // [64][68]   V (row-major)
    float* Ps = Vs + 64 * KS_STR;       // [64][128]  P^T swizzled

    int b  = blockIdx.z, h = blockIdx.y;
    int q0 = blockIdx.x * 128;
    int tid = threadIdx.x;
    int ty = tid & 15;                  // fast: c-groups (score) / d-groups (PV)
    int tx = tid >> 4;                  // r-groups (both phases)
    const float scale = 0.125f;         // 1/sqrt(64)
    size_t head_off = (size_t)h * 64;

    // ---- load Q tile (128 tok x 64 d) transposed into Qs, scaled ----
    {
        int tok = tid >> 1;
        int lc  = (tid & 1) * 4;
        const float* gq = g_q + ((size_t)(b*NS + q0 + tok)) * ND + head_off;
        #pragma unroll
        for (int st = 0; st < 8; st++) {
            int d = lc + 8*st;
            float4 v = *(const float4*)(gq + d);
            Qs[(d+0)*QS_STR + tok] = v.x * scale;
            Qs[(d+1)*QS_STR + tok] = v.y * scale;
            Qs[(d+2)*QS_STR + tok] = v.z * scale;
            Qs[(d+3)*QS_STR + tok] = v.w * scale;
        }
    }

    float m_run[8], l_run[8], accO[4][8];
    #pragma unroll
    for (int j = 0; j < 8; j++) { m_run[j] = -1e30f; l_run[j] = 0.f; }
    #pragma unroll
    for (int i = 0; i < 4; i++)
        #pragma unroll
        for (int j = 0; j < 8; j++) accO[i][j] = 0.f;

    int ltok = tid >> 2;                // K/V loader: 64 tok
    int llc  = (tid & 3) * 4;

    for (int kt0 = 0; kt0 < NS; kt0 += 64) {
        // ---- load K (transposed) and V (row-major) tiles ----
        {
            const float* gk = g_k + ((size_t)(b*NS + kt0 + ltok)) * ND + head_off;
            const float* gv = g_v + ((size_t)(b*NS + kt0 + ltok)) * ND + head_off;
            #pragma unroll
            for (int st = 0; st < 4; st++) {
                int d = llc + 16*st;
                float4 kv = *(const float4*)(gk + d);
                Ks[(d+0)*KS_STR + ltok] = kv.x;
                Ks[(d+1)*KS_STR + ltok] = kv.y;
                Ks[(d+2)*KS_STR + ltok] = kv.z;
                Ks[(d+3)*KS_STR + ltok] = kv.w;
                float4 vv = *(const float4*)(gv + d);
                *(float4*)&Vs[ltok*KS_STR + d] = vv;
            }
        }
        __syncthreads();

        // ---- score GEMM: S^T[c][r] ; c = 4*ty+i (64), r = 4*tx+j (+64) ----
        float sv[4][8];
        #pragma unroll
        for (int i = 0; i < 4; i++)
            #pragma unroll
            for (int j = 0; j < 8; j++) sv[i][j] = 0.f;

        #pragma unroll 8
        for (int kk = 0; kk < 64; kk++) {
            float4 a  = *(const float4*)&Ks[kk*KS_STR + 4*ty];
            float4 b0 = *(const float4*)&Qs[kk*QS_STR + 4*tx];
            float4 b1 = *(const float4*)&Qs[kk*QS_STR + 4*tx + 64];
            float av[4] = {a.x, a.y, a.z, a.w};
            float bv[8] = {b0.x,b0.y,b0.z,b0.w,b1.x,b1.y,b1.z,b1.w};
            #pragma unroll
            for (int i = 0; i < 4; i++)
                #pragma unroll
                for (int j = 0; j < 8; j++)
                    sv[i][j] += av[i] * bv[j];
        }

        // ---- online softmax: reduce over c = (i, ty-lanes) per r=j ----
        #pragma unroll
        for (int j = 0; j < 8; j++) {
            float mt = fmaxf(fmaxf(sv[0][j], sv[1][j]), fmaxf(sv[2][j], sv[3][j]));
            mt = fmaxf(mt, __shfl_xor_sync(0xffffffffu, mt, 1));
            mt = fmaxf(mt, __shfl_xor_sync(0xffffffffu, mt, 2));
            mt = fmaxf(mt, __shfl_xor_sync(0xffffffffu, mt, 4));
            mt = fmaxf(mt, __shfl_xor_sync(0xffffffffu, mt, 8));
            float mn   = fmaxf(m_run[j], mt);
            float corr = __expf(m_run[j] - mn);
            m_run[j] = mn;
            float ls = 0.f;
            #pragma unroll
            for (int i = 0; i < 4; i++) {
                sv[i][j] = __expf(sv[i][j] - mn);
                ls += sv[i][j];
            }
            ls += __shfl_xor_sync(0xffffffffu, ls, 1);
            ls += __shfl_xor_sync(0xffffffffu, ls, 2);
            ls += __shfl_xor_sync(0xffffffffu, ls, 4);
            ls += __shfl_xor_sync(0xffffffffu, ls, 8);
            l_run[j] = l_run[j] * corr + ls;
            #pragma unroll
            for (int i = 0; i < 4; i++) accO[i][j] *= corr;
        }

        // ---- store P^T to smem (swizzled slots: slot = tx ^ ((c>>2)&15)) ----
        {
            int sl = tx ^ ty;           // (c>>2)&15 == ty for c = 4*ty+i
            #pragma unroll
            for (int i = 0; i < 4; i++) {
                int c = 4*ty + i;
                float4 lo = make_float4(sv[i][0], sv[i][1], sv[i][2], sv[i][3]);
                float4 hi = make_float4(sv[i][4], sv[i][5], sv[i][6], sv[i][7]);
                *(float4*)&Ps[c*128 + 4*sl]        = lo;
                *(float4*)&Ps[c*128 + 4*(16 + sl)] = hi;
            }
        }
        __syncthreads();

        // ---- PV GEMM: O^T[d][r] += V^T P^T ; d = 4*ty+i, r = 4*tx+j (+64) ----
        #pragma unroll 8
        for (int kk = 0; kk < 64; kk++) {
            float4 a = *(const float4*)&Vs[kk*KS_STR + 4*ty];
            int key = (kk >> 2) & 15;
            float4 b0 = *(const float4*)&Ps[kk*128 + 4*(tx ^ key)];
            float4 b1 = *(const float4*)&Ps[kk*128 + 4*(16 + (tx ^ key))];
            float av[4] = {a.x, a.y, a.z, a.w};
            float bv[8] = {b0.x,b0.y,b0.z,b0.w,b1.x,b1.y,b1.z,b1.w};
            #pragma unroll
            for (int i = 0; i < 4; i++)
                #pragma unroll
                for (int j = 0; j < 8; j++)
                    accO[i][j] += av[i] * bv[j];
        }
        __syncthreads();
    }

    // ---- epilogue: divide by l, write O to g_att[(b*S + r)*D + h*64 + d] ----
    #pragma unroll
    for (int j = 0; j < 8; j++) {
        int r = (j < 4) ? (4*tx + j) : (64 + 4*tx + j - 4);
        float inv = 1.f / l_run[j];
        float4 o = make_float4(accO[0][j]*inv, accO[1][j]*inv,
                               accO[2][j]*inv, accO[3][j]*inv);
        *(float4*)(g_att + ((size_t)(b*NS + q0 + r)) * ND + head_off + 4*ty) = o;
    }
}

// ---------------------------------------------------------------------------
extern "C" void kernel_launch(void* const* d_in, const int* in_sizes, int n_in,
                              void* d_out, int out_size) {
    const float* x  = (const float*)d_in[0];
    const float* Wq = (const float*)d_in[1];
    const float* bq = (const float*)d_in[2];
    const float* Wk = (const float*)d_in[3];
    const float* bk = (const float*)d_in[4];
    const float* Wv = (const float*)d_in[5];
    const float* bv = (const float*)d_in[6];
    const float* Wo = (const float*)d_in[7];
    const float* bo = (const float*)d_in[8];
    float* out = (float*)d_out;

    float *xt, *q, *k, *v, *att;
    cudaGetSymbolAddress((void**)&xt,  g_xt);
    cudaGetSymbolAddress((void**)&q,   g_q);
    cudaGetSymbolAddress((void**)&k,   g_k);
    cudaGetSymbolAddress((void**)&v,   g_v);
    cudaGetSymbolAddress((void**)&att, g_att);

    dim3 pegrid(NS/32, ND/32, NB);
    pe_transpose_kernel<<<pegrid, dim3(32, 8)>>>(x);

    dim3 ggrid(ND/128, NTOK/128);
    sgemm_bias_kernel<0><<<ggrid, 256>>>(xt, Wq, bq, q);
    sgemm_bias_kernel<0><<<ggrid, 256>>>(xt, Wk, bk, k);
    sgemm_bias_kernel<0><<<ggrid, 256>>>(xt, Wv, bv, v);

    int attn_smem = (64*QS_STR + 64*KS_STR + 64*KS_STR + 64*128) * (int)sizeof(float);
    cudaFuncSetAttribute(flash_attn_kernel,
                         cudaFuncAttributeMaxDynamicSharedMemorySize, attn_smem);
    flash_attn_kernel<<<dim3(NS/128, NH, NB), 256, attn_smem>>>();

    sgemm_bias_kernel<1><<<ggrid, 256>>>(att, Wo, bo, out);
}

// round 14
// speedup vs baseline: 3.3875x; 1.3272x over previous
#include <cuda_runtime.h>
#include <cuda_bf16.h>
#include <math.h>
#include <stdint.h>

#define NB 4
#define ND 1024
#define NS 2048
#define NH 16
#define NTOK (NB*NS)   // 8192

// ---------------------------------------------------------------------------
// Scratch (allocation-free rule: device globals)
// ---------------------------------------------------------------------------
__device__ __nv_bfloat16 g_xh [(size_t)NTOK * ND];
__device__ __nv_bfloat16 g_xl [(size_t)NTOK * ND];
__device__ float         g_q  [(size_t)NTOK * ND];
__device__ float         g_k  [(size_t)NTOK * ND];
__device__ float         g_v  [(size_t)NTOK * ND];
__device__ __nv_bfloat16 g_ath[(size_t)NTOK * ND];
__device__ __nv_bfloat16 g_atl[(size_t)NTOK * ND];
__device__ __nv_bfloat16 g_wh [(size_t)4 * ND * ND];
__device__ __nv_bfloat16 g_wl [(size_t)4 * ND * ND];

// ---------------------------------------------------------------------------
// PTX helpers (sm_80-level ISA only: works at compute_103 virtual arch)
// ---------------------------------------------------------------------------
__device__ __forceinline__ uint32_t smem_u32(const void* p) {
    return (uint32_t)__cvta_generic_to_shared(p);
}
__device__ __forceinline__ void cpa16(uint32_t saddr, const void* g) {
    asm volatile("cp.async.cg.shared.global [%0], [%1], 16;"
                 :: "r"(saddr), "l"(g) : "memory");
}
__device__ __forceinline__ void cpa_commit() {
    asm volatile("cp.async.commit_group;" ::: "memory");
}
template<int N>
__device__ __forceinline__ void cpa_wait() {
    asm volatile("cp.async.wait_group %0;" :: "n"(N) : "memory");
}
__device__ __forceinline__ void ldsm4(uint32_t& r0, uint32_t& r1,
                                      uint32_t& r2, uint32_t& r3, uint32_t a) {
    asm volatile("ldmatrix.sync.aligned.m8n8.x4.shared.b16 {%0,%1,%2,%3}, [%4];"
                 : "=r"(r0), "=r"(r1), "=r"(r2), "=r"(r3) : "r"(a));
}
__device__ __forceinline__ void mma16816(float* c, const uint32_t* a,
                                         uint32_t b0, uint32_t b1) {
    asm volatile(
        "mma.sync.aligned.m16n8k16.row.col.f32.bf16.bf16.f32 "
        "{%0,%1,%2,%3}, {%4,%5,%6,%7}, {%8,%9}, {%0,%1,%2,%3};"
        : "+f"(c[0]), "+f"(c[1]), "+f"(c[2]), "+f"(c[3])
        : "r"(a[0]), "r"(a[1]), "r"(a[2]), "r"(a[3]), "r"(b0), "r"(b1));
}
__device__ __forceinline__ void split_bf16(float v, __nv_bfloat16& h, __nv_bfloat16& l) {
    h = __float2bfloat16(v);
    l = __float2bfloat16(v - __bfloat162float(h));
}

// ---------------------------------------------------------------------------
// Kernel 1: x[b,d,s] + PE(d,s) -> transposed bf16 hi/lo: g_xh/g_xl[(b*S+s)*D+d]
// ---------------------------------------------------------------------------
__global__ void pe_split_kernel(const float* __restrict__ x) {
    __shared__ float tile[32][33];
    int b  = blockIdx.z;
    int d0 = blockIdx.y * 32;
    int s0 = blockIdx.x * 32;
    int tx = threadIdx.x, ty = threadIdx.y;
    #pragma unroll
    for (int i = 0; i < 32; i += 8) {
        int d = d0 + ty + i;
        int s = s0 + tx;
        float v = x[(size_t)b * ND * NS + (size_t)d * NS + s];
        float base = (float)(d & ~1);
        float freq = __expf(base * (-9.210340371976184f / (float)ND));
        float ang  = (float)s * freq;
        v += (d & 1) ? cosf(ang) : sinf(ang);
        tile[ty + i][tx] = v;
    }
    __syncthreads();
    #pragma unroll
    for (int i = 0; i < 32; i += 8) {
        int s = s0 + ty + i;
        int d = d0 + tx;
        float v = tile[tx][ty + i];
        __nv_bfloat16 h, l;
        split_bf16(v, h, l);
        size_t o = ((size_t)b * NS + s) * ND + d;
        g_xh[o] = h;
        g_xl[o] = l;
    }
}

// ---------------------------------------------------------------------------
// Kernel 1b: weight split W (fp32 [N,K]) -> hi/lo bf16
// ---------------------------------------------------------------------------
__global__ void wsplit_kernel(const float* __restrict__ w,
                              __nv_bfloat16* __restrict__ h,
                              __nv_bfloat16* __restrict__ l) {
    int i = (blockIdx.x * blockDim.x + threadIdx.x) * 4;
    float4 v = *(const float4*)(w + i);
    __nv_bfloat16 h0,h1,h2,h3,l0,l1,l2,l3;
    split_bf16(v.x, h0, l0); split_bf16(v.y, h1, l1);
    split_bf16(v.z, h2, l2); split_bf16(v.w, h3, l3);
    ((__nv_bfloat162*)(h + i))[0] = __halves2bfloat162(h0, h1);
    ((__nv_bfloat162*)(h + i))[1] = __halves2bfloat162(h2, h3);
    ((__nv_bfloat162*)(l + i))[0] = __halves2bfloat162(l0, l1);
    ((__nv_bfloat162*)(l + i))[1] = __halves2bfloat162(l2, l3);
}

// ---------------------------------------------------------------------------
// Kernel 2: bf16x3 GEMM via mma.sync (HMMA).  C = A*W^T + bias.
// M=8192, N=K=1024. CTA: 128x128, 8 warps (warp tile 32x64), BK=32,
// cp.async double-buffered smem. Rows padded to 80 B -> conflict-free ldmatrix.
// TOUT=1: write transposed to out[b, n, s].
// ---------------------------------------------------------------------------
#define ROWB   80                       // bytes per smem row (32 bf16 + pad)
#define TILEB  (128 * ROWB)             // 10240 B per tile
#define T_AH   0
#define T_AL   (1 * TILEB)
#define T_WH   (2 * TILEB)
#define T_WL   (3 * TILEB)
#define BUFB   (4 * TILEB)              // 40960 B per stage
#define GEMM_SMEM (2 * BUFB)            // 81920 B

template<int TOUT>
__global__ void __launch_bounds__(256, 2) tc_gemm_kernel(
    const __nv_bfloat16* __restrict__ Ah, const __nv_bfloat16* __restrict__ Al,
    const __nv_bfloat16* __restrict__ Wh, const __nv_bfloat16* __restrict__ Wl,
    const float* __restrict__ bias, float* __restrict__ C)
{
    extern __shared__ __align__(128) char smem[];
    uint32_t sb = smem_u32(smem);
    int tid  = threadIdx.x;
    int lane = tid & 31;
    int wid  = tid >> 5;
    int col0 = blockIdx.x * 128;
    int row0 = blockIdx.y * 128;

    // loader: 2 iters x (r = idx>>2, c = idx&3) covers 128 rows x 4 16B-chunks
    int lr0 = tid >> 2;           // iter 0 row (0..63)
    int lcc = (tid & 3);          // chunk 0..3
    const char* gAh = (const char*)Ah;
    const char* gAl = (const char*)Al;
    const char* gWh = (const char*)Wh;
    const char* gWl = (const char*)Wl;

    auto load_chunk = [&](int kc, int buf) {
        int k0 = kc * 32;
        uint32_t sbb = sb + buf * BUFB;
        #pragma unroll
        for (int t = 0; t < 2; t++) {
            int r = lr0 + t * 64;
            uint32_t so = (uint32_t)(r * ROWB + lcc * 16);
            size_t ga = ((size_t)(row0 + r) * ND + k0 + lcc * 8) * 2;
            size_t gw = ((size_t)(col0 + r) * ND + k0 + lcc * 8) * 2;
            cpa16(sbb + T_AH + so, gAh + ga);
            cpa16(sbb + T_AL + so, gAl + ga);
            cpa16(sbb + T_WH + so, gWh + gw);
            cpa16(sbb + T_WL + so, gWl + gw);
        }
    };

    // warp tiling
    int wm = (wid & 3) * 32;      // m offset within CTA tile
    int wn = (wid >> 2) * 64;     // n offset within CTA tile
    int g  = lane >> 3;           // ldmatrix group 0..3
    int gi = lane & 7;

    // A lane offsets (per m-tile, per k16-step): groups (m0-7,k0)(m8-15,k0)(m0-7,k8)(m8-15,k8)
    uint32_t a_off[2];
    #pragma unroll
    for (int mt = 0; mt < 2; mt++) {
        int r = wm + mt * 16 + (g & 1) * 8 + gi;
        a_off[mt] = (uint32_t)(r * ROWB + (g >> 1) * 16);
    }
    // B lane offsets (per n-pair): groups (n0-7,k0)(n0-7,k8)(n8-15,k0)(n8-15,k8)
    uint32_t b_off[4];
    #pragma unroll
    for (int np = 0; np < 4; np++) {
        int r = wn + np * 16 + (g >> 1) * 8 + gi;
        b_off[np] = (uint32_t)(r * ROWB + (g & 1) * 16);
    }

    float acc[2][8][4];
    #pragma unroll
    for (int mt = 0; mt < 2; mt++)
        #pragma unroll
        for (int nt = 0; nt < 8; nt++)
            #pragma unroll
            for (int e = 0; e < 4; e++) acc[mt][nt][e] = 0.f;

    load_chunk(0, 0);
    cpa_commit();

    const int NCHUNK = ND / 32;   // 32
    for (int kc = 0; kc < NCHUNK; kc++) {
        int buf = kc & 1;
        if (kc + 1 < NCHUNK) {
            load_chunk(kc + 1, buf ^ 1);
            cpa_commit();
            cpa_wait<1>();
        } else {
            cpa_wait<0>();
        }
        __syncthreads();

        uint32_t sbb = sb + buf * BUFB;
        #pragma unroll
        for (int s = 0; s < 2; s++) {
            uint32_t ko = (uint32_t)(s * 32);   // 16 bf16 = 32 B per k16 step
            uint32_t ah[2][4], al[2][4];
            #pragma unroll
            for (int mt = 0; mt < 2; mt++) {
                ldsm4(ah[mt][0], ah[mt][1], ah[mt][2], ah[mt][3],
                      sbb + T_AH + a_off[mt] + ko);
                ldsm4(al[mt][0], al[mt][1], al[mt][2], al[mt][3],
                      sbb + T_AL + a_off[mt] + ko);
            }
            #pragma unroll
            for (int np = 0; np < 4; np++) {
                uint32_t bh0, bh1, bh2, bh3, bl0, bl1, bl2, bl3;
                ldsm4(bh0, bh1, bh2, bh3, sbb + T_WH + b_off[np] + ko);
                ldsm4(bl0, bl1, bl2, bl3, sbb + T_WL + b_off[np] + ko);
                #pragma unroll
                for (int mt = 0; mt < 2; mt++) {
                    mma16816(acc[mt][np*2+0], ah[mt], bh0, bh1);
                    mma16816(acc[mt][np*2+1], ah[mt], bh2, bh3);
                    mma16816(acc[mt][np*2+0], ah[mt], bl0, bl1);
                    mma16816(acc[mt][np*2+1], ah[mt], bl2, bl3);
                    mma16816(acc[mt][np*2+0], al[mt], bh0, bh1);
                    mma16816(acc[mt][np*2+1], al[mt], bh2, bh3);
                }
            }
        }
        __syncthreads();
    }

    // epilogue: c-fragment lane l: {c0,c1} = C[l/4][2(l%4)..+1], {c2,c3} = row+8
    int cr = lane >> 2;
    int cc = (lane & 3) * 2;
    #pragma unroll
    for (int nt = 0; nt < 8; nt++) {
        int col = col0 + wn + nt * 8 + cc;
        float b0 = __ldg(&bias[col]);
        float b1 = __ldg(&bias[col + 1]);
        #pragma unroll
        for (int mt = 0; mt < 2; mt++) {
            int row = row0 + wm + mt * 16 + cr;
            float v00 = acc[mt][nt][0] + b0;
            float v01 = acc[mt][nt][1] + b1;
            float v10 = acc[mt][nt][2] + b0;
            float v11 = acc[mt][nt][3] + b1;
            if (TOUT) {
                int bb0 = row >> 11,       s0i = row & (NS - 1);
                int bb1 = (row + 8) >> 11, s1i = (row + 8) & (NS - 1);
                size_t o0 = ((size_t)bb0 * ND + col) * NS + s0i;
                size_t o1 = ((size_t)bb1 * ND + col) * NS + s1i;
                C[o0]      = v00;
                C[o0 + NS] = v01;
                C[o1]      = v10;
                C[o1 + NS] = v11;
            } else {
                *(float2*)&C[(size_t)row * ND + col]       = make_float2(v00, v01);
                *(float2*)&C[(size_t)(row + 8) * ND + col] = make_float2(v10, v11);
            }
        }
    }
}

// ---------------------------------------------------------------------------
// Kernel 3: flash attention (fp32 SIMT), epilogue emits bf16 hi/lo for O-proj.
// ---------------------------------------------------------------------------
#define QS_STR 132
#define KS_STR 68

__global__ void __launch_bounds__(256, 2) flash_attn_kernel() {
    extern __shared__ float sm[];
    float* Qs = sm;                     // [64][132]  Q^T (d-major), pre-scaled
    float* Ks = Qs + 64 * QS_STR;       // [64][68]   K^T (d-major)
    float* Vs = Ks + 64 * KS_STR;       // [64][68]   V (row-major)
    float* Ps = Vs + 64 * KS_STR;       // [64][128]  P^T swizzled

    int b  = blockIdx.z, h = blockIdx.y;
    int q0 = blockIdx.x * 128;
    int tid = threadIdx.x;
    int ty = tid & 15;
    int tx = tid >> 4;
    const float scale = 0.125f;
    size_t head_off = (size_t)h * 64;

    {
        int tok = tid >> 1;
        int lc  = (tid & 1) * 4;
        const float* gq = g_q + ((size_t)(b*NS + q0 + tok)) * ND + head_off;
        #pragma unroll
        for (int st = 0; st < 8; st++) {
            int d = lc + 8*st;
            float4 v = *(const float4*)(gq + d);
            Qs[(d+0)*QS_STR + tok] = v.x * scale;
            Qs[(d+1)*QS_STR + tok] = v.y * scale;
            Qs[(d+2)*QS_STR + tok] = v.z * scale;
            Qs[(d+3)*QS_STR + tok] = v.w * scale;
        }
    }

    float m_run[8], l_run[8], accO[4][8];
    #pragma unroll
    for (int j = 0; j < 8; j++) { m_run[j] = -1e30f; l_run[j] = 0.f; }
    #pragma unroll
    for (int i = 0; i < 4; i++)
        #pragma unroll
        for (int j = 0; j < 8; j++) accO[i][j] = 0.f;

    int ltok = tid >> 2;
    int llc  = (tid & 3) * 4;

    for (int kt0 = 0; kt0 < NS; kt0 += 64) {
        {
            const float* gk = g_k + ((size_t)(b*NS + kt0 + ltok)) * ND + head_off;
            const float* gv = g_v + ((size_t)(b*NS + kt0 + ltok)) * ND + head_off;
            #pragma unroll
            for (int st = 0; st < 4; st++) {
                int d = llc + 16*st;
                float4 kv = *(const float4*)(gk + d);
                Ks[(d+0)*KS_STR + ltok] = kv.x;
                Ks[(d+1)*KS_STR + ltok] = kv.y;
                Ks[(d+2)*KS_STR + ltok] = kv.z;
                Ks[(d+3)*KS_STR + ltok] = kv.w;
                float4 vv = *(const float4*)(gv + d);
                *(float4*)&Vs[ltok*KS_STR + d] = vv;
            }
        }
        __syncthreads();

        float sv[4][8];
        #pragma unroll
        for (int i = 0; i < 4; i++)
            #pragma unroll
            for (int j = 0; j < 8; j++) sv[i][j] = 0.f;

        #pragma unroll 8
        for (int kk = 0; kk < 64; kk++) {
            float4 a  = *(const float4*)&Ks[kk*KS_STR + 4*ty];
            float4 b0 = *(const float4*)&Qs[kk*QS_STR + 4*tx];
            float4 b1 = *(const float4*)&Qs[kk*QS_STR + 4*tx + 64];
            float av[4] = {a.x, a.y, a.z, a.w};
            float bv[8] = {b0.x,b0.y,b0.z,b0.w,b1.x,b1.y,b1.z,b1.w};
            #pragma unroll
            for (int i = 0; i < 4; i++)
                #pragma unroll
                for (int j = 0; j < 8; j++)
                    sv[i][j] += av[i] * bv[j];
        }

        #pragma unroll
        for (int j = 0; j < 8; j++) {
            float mt = fmaxf(fmaxf(sv[0][j], sv[1][j]), fmaxf(sv[2][j], sv[3][j]));
            mt = fmaxf(mt, __shfl_xor_sync(0xffffffffu, mt, 1));
            mt = fmaxf(mt, __shfl_xor_sync(0xffffffffu, mt, 2));
            mt = fmaxf(mt, __shfl_xor_sync(0xffffffffu, mt, 4));
            mt = fmaxf(mt, __shfl_xor_sync(0xffffffffu, mt, 8));
            float mn   = fmaxf(m_run[j], mt);
            float corr = __expf(m_run[j] - mn);
            m_run[j] = mn;
            float ls = 0.f;
            #pragma unroll
            for (int i = 0; i < 4; i++) {
                sv[i][j] = __expf(sv[i][j] - mn);
                ls += sv[i][j];
            }
            ls += __shfl_xor_sync(0xffffffffu, ls, 1);
            ls += __shfl_xor_sync(0xffffffffu, ls, 2);
            ls += __shfl_xor_sync(0xffffffffu, ls, 4);
            ls += __shfl_xor_sync(0xffffffffu, ls, 8);
            l_run[j] = l_run[j] * corr + ls;
            #pragma unroll
            for (int i = 0; i < 4; i++) accO[i][j] *= corr;
        }

        {
            int sl = tx ^ ty;
            #pragma unroll
            for (int i = 0; i < 4; i++) {
                int c = 4*ty + i;
                float4 lo = make_float4(sv[i][0], sv[i][1], sv[i][2], sv[i][3]);
                float4 hi = make_float4(sv[i][4], sv[i][5], sv[i][6], sv[i][7]);
                *(float4*)&Ps[c*128 + 4*sl]        = lo;
                *(float4*)&Ps[c*128 + 4*(16 + sl)] = hi;
            }
        }
        __syncthreads();

        #pragma unroll 8
        for (int kk = 0; kk < 64; kk++) {
            float4 a = *(const float4*)&Vs[kk*KS_STR + 4*ty];
            int key = (kk >> 2) & 15;
            float4 b0 = *(const float4*)&Ps[kk*128 + 4*(tx ^ key)];
            float4 b1 = *(const float4*)&Ps[kk*128 + 4*(16 + (tx ^ key))];
            float av[4] = {a.x, a.y, a.z, a.w};
            float bv[8] = {b0.x,b0.y,b0.z,b0.w,b1.x,b1.y,b1.z,b1.w};
            #pragma unroll
            for (int i = 0; i < 4; i++)
                #pragma unroll
                for (int j = 0; j < 8; j++)
                    accO[i][j] += av[i] * bv[j];
        }
        __syncthreads();
    }

    #pragma unroll
    for (int j = 0; j < 8; j++) {
        int r = (j < 4) ? (4*tx + j) : (64 + 4*tx + j - 4);
        float inv = 1.f / l_run[j];
        float o0 = accO[0][j]*inv, o1 = accO[1][j]*inv;
        float o2 = accO[2][j]*inv, o3 = accO[3][j]*inv;
        __nv_bfloat16 h0,h1,h2,h3,l0,l1,l2,l3;
        split_bf16(o0,h0,l0); split_bf16(o1,h1,l1);
        split_bf16(o2,h2,l2); split_bf16(o3,h3,l3);
        size_t off = ((size_t)(b*NS + q0 + r)) * ND + head_off + 4*ty;
        ((__nv_bfloat162*)(g_ath + off))[0] = __halves2bfloat162(h0,h1);
        ((__nv_bfloat162*)(g_ath + off))[1] = __halves2bfloat162(h2,h3);
        ((__nv_bfloat162*)(g_atl + off))[0] = __halves2bfloat162(l0,l1);
        ((__nv_bfloat162*)(g_atl + off))[1] = __halves2bfloat162(l2,l3);
    }
}

// ---------------------------------------------------------------------------
extern "C" void kernel_launch(void* const* d_in, const int* in_sizes, int n_in,
                              void* d_out, int out_size) {
    const float* x  = (const float*)d_in[0];
    const float* Wq = (const float*)d_in[1];
    const float* bq = (const float*)d_in[2];
    const float* Wk = (const float*)d_in[3];
    const float* bk = (const float*)d_in[4];
    const float* Wv = (const float*)d_in[5];
    const float* bv = (const float*)d_in[6];
    const float* Wo = (const float*)d_in[7];
    const float* bo = (const float*)d_in[8];
    float* out = (float*)d_out;

    __nv_bfloat16 *xh, *xl, *ath, *atl, *wh, *wl;
    float *q, *k, *v;
    cudaGetSymbolAddress((void**)&xh,  g_xh);
    cudaGetSymbolAddress((void**)&xl,  g_xl);
    cudaGetSymbolAddress((void**)&q,   g_q);
    cudaGetSymbolAddress((void**)&k,   g_k);
    cudaGetSymbolAddress((void**)&v,   g_v);
    cudaGetSymbolAddress((void**)&ath, g_ath);
    cudaGetSymbolAddress((void**)&atl, g_atl);
    cudaGetSymbolAddress((void**)&wh,  g_wh);
    cudaGetSymbolAddress((void**)&wl,  g_wl);

    const size_t WSZ = (size_t)ND * ND;

    cudaFuncSetAttribute(tc_gemm_kernel<0>,
                         cudaFuncAttributeMaxDynamicSharedMemorySize, GEMM_SMEM);
    cudaFuncSetAttribute(tc_gemm_kernel<1>,
                         cudaFuncAttributeMaxDynamicSharedMemorySize, GEMM_SMEM);
    int attn_smem = (64*QS_STR + 64*KS_STR + 64*KS_STR + 64*128) * (int)sizeof(float);
    cudaFuncSetAttribute(flash_attn_kernel,
                         cudaFuncAttributeMaxDynamicSharedMemorySize, attn_smem);

    // PE + transpose + bf16 split
    pe_split_kernel<<<dim3(NS/32, ND/32, NB), dim3(32, 8)>>>(x);

    // weight splits
    wsplit_kernel<<<ND*ND/1024, 256>>>(Wq, wh + 0*WSZ, wl + 0*WSZ);
    wsplit_kernel<<<ND*ND/1024, 256>>>(Wk, wh + 1*WSZ, wl + 1*WSZ);
    wsplit_kernel<<<ND*ND/1024, 256>>>(Wv, wh + 2*WSZ, wl + 2*WSZ);
    wsplit_kernel<<<ND*ND/1024, 256>>>(Wo, wh + 3*WSZ, wl + 3*WSZ);

    // Q/K/V projections (HMMA)
    dim3 ggrid(ND/128, NTOK/128);
    tc_gemm_kernel<0><<<ggrid, 256, GEMM_SMEM>>>(xh, xl, wh + 0*WSZ, wl + 0*WSZ, bq, q);
    tc_gemm_kernel<0><<<ggrid, 256, GEMM_SMEM>>>(xh, xl, wh + 1*WSZ, wl + 1*WSZ, bk, k);
    tc_gemm_kernel<0><<<ggrid, 256, GEMM_SMEM>>>(xh, xl, wh + 2*WSZ, wl + 2*WSZ, bv, v);

    // attention
    flash_attn_kernel<<<dim3(NS/128, NH, NB), 256, attn_smem>>>();

    // O-projection with fused [B,D,S] transpose epilogue
    tc_gemm_kernel<1><<<ggrid, 256, GEMM_SMEM>>>(ath, atl, wh + 3*WSZ, wl + 3*WSZ, bo, out);
}

// round 15
// speedup vs baseline: 6.0902x; 1.7978x over previous
#include <cuda_runtime.h>
#include <cuda_bf16.h>
#include <math.h>
#include <stdint.h>

#define NB 4
#define ND 1024
#define NS 2048
#define NH 16
#define NTOK (NB*NS)   // 8192

// ---------------------------------------------------------------------------
// Scratch (allocation-free rule: device globals)
// ---------------------------------------------------------------------------
__device__ __nv_bfloat16 g_xh [(size_t)NTOK * ND];
__device__ __nv_bfloat16 g_xl [(size_t)NTOK * ND];
__device__ __nv_bfloat16 g_qh [(size_t)NTOK * ND];
__device__ __nv_bfloat16 g_ql [(size_t)NTOK * ND];
__device__ __nv_bfloat16 g_kh [(size_t)NTOK * ND];
__device__ __nv_bfloat16 g_kl [(size_t)NTOK * ND];
__device__ __nv_bfloat16 g_vh [(size_t)NTOK * ND];
__device__ __nv_bfloat16 g_vl [(size_t)NTOK * ND];
__device__ __nv_bfloat16 g_ath[(size_t)NTOK * ND];
__device__ __nv_bfloat16 g_atl[(size_t)NTOK * ND];
__device__ __nv_bfloat16 g_wh [(size_t)4 * ND * ND];
__device__ __nv_bfloat16 g_wl [(size_t)4 * ND * ND];

// ---------------------------------------------------------------------------
// PTX helpers (sm_80-level ISA only: works at compute_103 virtual arch)
// ---------------------------------------------------------------------------
__device__ __forceinline__ uint32_t smem_u32(const void* p) {
    return (uint32_t)__cvta_generic_to_shared(p);
}
__device__ __forceinline__ void cpa16(uint32_t saddr, const void* g) {
    asm volatile("cp.async.cg.shared.global [%0], [%1], 16;"
                 :: "r"(saddr), "l"(g) : "memory");
}
__device__ __forceinline__ void cpa_commit() {
    asm volatile("cp.async.commit_group;" ::: "memory");
}
template<int N>
__device__ __forceinline__ void cpa_wait() {
    asm volatile("cp.async.wait_group %0;" :: "n"(N) : "memory");
}
__device__ __forceinline__ void ldsm4(uint32_t& r0, uint32_t& r1,
                                      uint32_t& r2, uint32_t& r3, uint32_t a) {
    asm volatile("ldmatrix.sync.aligned.m8n8.x4.shared.b16 {%0,%1,%2,%3}, [%4];"
                 : "=r"(r0), "=r"(r1), "=r"(r2), "=r"(r3) : "r"(a));
}
__device__ __forceinline__ void ldsm4t(uint32_t& r0, uint32_t& r1,
                                       uint32_t& r2, uint32_t& r3, uint32_t a) {
    asm volatile("ldmatrix.sync.aligned.m8n8.x4.trans.shared.b16 {%0,%1,%2,%3}, [%4];"
                 : "=r"(r0), "=r"(r1), "=r"(r2), "=r"(r3) : "r"(a));
}
__device__ __forceinline__ void mma16816(float* c, const uint32_t* a,
                                         uint32_t b0, uint32_t b1) {
    asm volatile(
        "mma.sync.aligned.m16n8k16.row.col.f32.bf16.bf16.f32 "
        "{%0,%1,%2,%3}, {%4,%5,%6,%7}, {%8,%9}, {%0,%1,%2,%3};"
        : "+f"(c[0]), "+f"(c[1]), "+f"(c[2]), "+f"(c[3])
        : "r"(a[0]), "r"(a[1]), "r"(a[2]), "r"(a[3]), "r"(b0), "r"(b1));
}
__device__ __forceinline__ void split_bf16(float v, __nv_bfloat16& h, __nv_bfloat16& l) {
    h = __float2bfloat16(v);
    l = __float2bfloat16(v - __bfloat162float(h));
}
// split two floats into packed bf16x2 hi + lo words (x = first arg = low half)
__device__ __forceinline__ void split2(float a, float b, uint32_t& hi, uint32_t& lo) {
    __nv_bfloat16 ha = __float2bfloat16(a), hb = __float2bfloat16(b);
    float ra = a - __bfloat162float(ha), rb = b - __bfloat162float(hb);
    __nv_bfloat162 H = __halves2bfloat162(ha, hb);
    __nv_bfloat162 L = __halves2bfloat162(__float2bfloat16(ra), __float2bfloat16(rb));
    hi = *reinterpret_cast<uint32_t*>(&H);
    lo = *reinterpret_cast<uint32_t*>(&L);
}

// ---------------------------------------------------------------------------
// Kernel 1: x[b,d,s] + PE(d,s) -> transposed bf16 hi/lo: g_xh/g_xl[(b*S+s)*D+d]
// ---------------------------------------------------------------------------
__global__ void pe_split_kernel(const float* __restrict__ x) {
    __shared__ float tile[32][33];
    int b  = blockIdx.z;
    int d0 = blockIdx.y * 32;
    int s0 = blockIdx.x * 32;
    int tx = threadIdx.x, ty = threadIdx.y;
    #pragma unroll
    for (int i = 0; i < 32; i += 8) {
        int d = d0 + ty + i;
        int s = s0 + tx;
        float v = x[(size_t)b * ND * NS + (size_t)d * NS + s];
        float base = (float)(d & ~1);
        float freq = __expf(base * (-9.210340371976184f / (float)ND));
        float ang  = (float)s * freq;
        v += (d & 1) ? cosf(ang) : sinf(ang);
        tile[ty + i][tx] = v;
    }
    __syncthreads();
    #pragma unroll
    for (int i = 0; i < 32; i += 8) {
        int s = s0 + ty + i;
        int d = d0 + tx;
        float v = tile[tx][ty + i];
        __nv_bfloat16 h, l;
        split_bf16(v, h, l);
        size_t o = ((size_t)b * NS + s) * ND + d;
        g_xh[o] = h;
        g_xl[o] = l;
    }
}

// ---------------------------------------------------------------------------
// Kernel 1b: weight split W (fp32 [N,K]) * scale -> hi/lo bf16
// ---------------------------------------------------------------------------
__global__ void wsplit_kernel(const float* __restrict__ w,
                              __nv_bfloat16* __restrict__ h,
                              __nv_bfloat16* __restrict__ l, float scale) {
    int i = (blockIdx.x * blockDim.x + threadIdx.x) * 4;
    float4 v = *(const float4*)(w + i);
    __nv_bfloat16 h0,h1,h2,h3,l0,l1,l2,l3;
    split_bf16(v.x*scale, h0, l0); split_bf16(v.y*scale, h1, l1);
    split_bf16(v.z*scale, h2, l2); split_bf16(v.w*scale, h3, l3);
    ((__nv_bfloat162*)(h + i))[0] = __halves2bfloat162(h0, h1);
    ((__nv_bfloat162*)(h + i))[1] = __halves2bfloat162(h2, h3);
    ((__nv_bfloat162*)(l + i))[0] = __halves2bfloat162(l0, l1);
    ((__nv_bfloat162*)(l + i))[1] = __halves2bfloat162(l2, l3);
}

// ---------------------------------------------------------------------------
// Kernel 2: bf16x3 GEMM via mma.sync (HMMA).  C = A*W^T + bias*bscale.
// MODE 1: f32 out transposed to [B,D,S].  MODE 2: bf16 hi/lo pair outputs.
// ---------------------------------------------------------------------------
#define ROWB   80                       // bytes per smem row (32 bf16 + pad)
#define TILEB  (128 * ROWB)
#define T_AH   0
#define T_AL   (1 * TILEB)
#define T_WH   (2 * TILEB)
#define T_WL   (3 * TILEB)
#define BUFB   (4 * TILEB)
#define GEMM_SMEM (2 * BUFB)            // 81920 B

template<int MODE>
__global__ void __launch_bounds__(256, 2) tc_gemm_kernel(
    const __nv_bfloat16* __restrict__ Ah, const __nv_bfloat16* __restrict__ Al,
    const __nv_bfloat16* __restrict__ Wh, const __nv_bfloat16* __restrict__ Wl,
    const float* __restrict__ bias, float bscale, float* __restrict__ C,
    __nv_bfloat16* __restrict__ Ch, __nv_bfloat16* __restrict__ Cl)
{
    extern __shared__ __align__(128) char smem[];
    uint32_t sb = smem_u32(smem);
    int tid  = threadIdx.x;
    int lane = tid & 31;
    int wid  = tid >> 5;
    int col0 = blockIdx.x * 128;
    int row0 = blockIdx.y * 128;

    int lr0 = tid >> 2;
    int lcc = (tid & 3);
    const char* gAh = (const char*)Ah;
    const char* gAl = (const char*)Al;
    const char* gWh = (const char*)Wh;
    const char* gWl = (const char*)Wl;

    auto load_chunk = [&](int kc, int buf) {
        int k0 = kc * 32;
        uint32_t sbb = sb + buf * BUFB;
        #pragma unroll
        for (int t = 0; t < 2; t++) {
            int r = lr0 + t * 64;
            uint32_t so = (uint32_t)(r * ROWB + lcc * 16);
            size_t ga = ((size_t)(row0 + r) * ND + k0 + lcc * 8) * 2;
            size_t gw = ((size_t)(col0 + r) * ND + k0 + lcc * 8) * 2;
            cpa16(sbb + T_AH + so, gAh + ga);
            cpa16(sbb + T_AL + so, gAl + ga);
            cpa16(sbb + T_WH + so, gWh + gw);
            cpa16(sbb + T_WL + so, gWl + gw);
        }
    };

    int wm = (wid & 3) * 32;
    int wn = (wid >> 2) * 64;
    int g  = lane >> 3;
    int gi = lane & 7;

    uint32_t a_off[2];
    #pragma unroll
    for (int mt = 0; mt < 2; mt++) {
        int r = wm + mt * 16 + (g & 1) * 8 + gi;
        a_off[mt] = (uint32_t)(r * ROWB + (g >> 1) * 16);
    }
    uint32_t b_off[4];
    #pragma unroll
    for (int np = 0; np < 4; np++) {
        int r = wn + np * 16 + (g >> 1) * 8 + gi;
        b_off[np] = (uint32_t)(r * ROWB + (g & 1) * 16);
    }

    float acc[2][8][4];
    #pragma unroll
    for (int mt = 0; mt < 2; mt++)
        #pragma unroll
        for (int nt = 0; nt < 8; nt++)
            #pragma unroll
            for (int e = 0; e < 4; e++) acc[mt][nt][e] = 0.f;

    load_chunk(0, 0);
    cpa_commit();

    const int NCHUNK = ND / 32;
    for (int kc = 0; kc < NCHUNK; kc++) {
        int buf = kc & 1;
        if (kc + 1 < NCHUNK) {
            load_chunk(kc + 1, buf ^ 1);
            cpa_commit();
            cpa_wait<1>();
        } else {
            cpa_wait<0>();
        }
        __syncthreads();

        uint32_t sbb = sb + buf * BUFB;
        #pragma unroll
        for (int s = 0; s < 2; s++) {
            uint32_t ko = (uint32_t)(s * 32);
            uint32_t ah[2][4], al[2][4];
            #pragma unroll
            for (int mt = 0; mt < 2; mt++) {
                ldsm4(ah[mt][0], ah[mt][1], ah[mt][2], ah[mt][3],
                      sbb + T_AH + a_off[mt] + ko);
                ldsm4(al[mt][0], al[mt][1], al[mt][2], al[mt][3],
                      sbb + T_AL + a_off[mt] + ko);
            }
            #pragma unroll
            for (int np = 0; np < 4; np++) {
                uint32_t bh0, bh1, bh2, bh3, bl0, bl1, bl2, bl3;
                ldsm4(bh0, bh1, bh2, bh3, sbb + T_WH + b_off[np] + ko);
                ldsm4(bl0, bl1, bl2, bl3, sbb + T_WL + b_off[np] + ko);
                #pragma unroll
                for (int mt = 0; mt < 2; mt++) {
                    mma16816(acc[mt][np*2+0], ah[mt], bh0, bh1);
                    mma16816(acc[mt][np*2+1], ah[mt], bh2, bh3);
                    mma16816(acc[mt][np*2+0], ah[mt], bl0, bl1);
                    mma16816(acc[mt][np*2+1], ah[mt], bl2, bl3);
                    mma16816(acc[mt][np*2+0], al[mt], bh0, bh1);
                    mma16816(acc[mt][np*2+1], al[mt], bh2, bh3);
                }
            }
        }
        __syncthreads();
    }

    int cr = lane >> 2;
    int cc = (lane & 3) * 2;
    #pragma unroll
    for (int nt = 0; nt < 8; nt++) {
        int col = col0 + wn + nt * 8 + cc;
        float b0 = __ldg(&bias[col]) * bscale;
        float b1 = __ldg(&bias[col + 1]) * bscale;
        #pragma unroll
        for (int mt = 0; mt < 2; mt++) {
            int row = row0 + wm + mt * 16 + cr;
            float v00 = acc[mt][nt][0] + b0;
            float v01 = acc[mt][nt][1] + b1;
            float v10 = acc[mt][nt][2] + b0;
            float v11 = acc[mt][nt][3] + b1;
            if (MODE == 1) {
                int bb0 = row >> 11,       s0i = row & (NS - 1);
                int bb1 = (row + 8) >> 11, s1i = (row + 8) & (NS - 1);
                size_t o0 = ((size_t)bb0 * ND + col) * NS + s0i;
                size_t o1 = ((size_t)bb1 * ND + col) * NS + s1i;
                C[o0]      = v00;
                C[o0 + NS] = v01;
                C[o1]      = v10;
                C[o1 + NS] = v11;
            } else {
                uint32_t h0, l0, h1, l1;
                split2(v00, v01, h0, l0);
                split2(v10, v11, h1, l1);
                size_t o0 = (size_t)row * ND + col;
                size_t o1 = (size_t)(row + 8) * ND + col;
                *(uint32_t*)&Ch[o0] = h0;
                *(uint32_t*)&Cl[o0] = l0;
                *(uint32_t*)&Ch[o1] = h1;
                *(uint32_t*)&Cl[o1] = l1;
            }
        }
    }
}

// ---------------------------------------------------------------------------
// Kernel 3: flash attention via mma.sync, hi/lo bf16 both GEMMs.
// CTA = 128 q-rows x one (b,h). 8 warps x 16 q-rows. 64-key tiles,
// cp.async double-buffered. V consumed via ldmatrix.trans (no smem transpose).
// P fragments built in-register from S C-fragments (C-frag == A-frag layout).
// Q pre-scaled by 1/8 (folded into Wq/bq at wsplit time).
// ---------------------------------------------------------------------------
#define AT_ROW  72                       // bf16 row stride (64 + 8): conflict-free
#define AT_TILE (64 * AT_ROW * 2)        // 9216 B
#define A_KH    0
#define A_KL    (1 * AT_TILE)
#define A_VH    (2 * AT_TILE)
#define A_VL    (3 * AT_TILE)
#define A_STAGE (4 * AT_TILE)            // 36864 B
#define ATT_SMEM (2 * A_STAGE)           // 73728 B

__global__ void __launch_bounds__(256, 2) mma_attn_kernel() {
    extern __shared__ __align__(128) char smem[];
    uint32_t sb = smem_u32(smem);
    int b   = blockIdx.z, h = blockIdx.y;
    int q0g = blockIdx.x * 128;
    int tid = threadIdx.x;
    int lane = tid & 31;
    int wid  = tid >> 5;
    size_t hoff = (size_t)h * 64;
    int g  = lane >> 3;
    int gi = lane & 7;

    // ---- stage Q (hi/lo) into stage-0 smem, then build A-fragments ----
    {
        int r  = tid >> 1;
        int c0 = (tid & 1) * 4;
        #pragma unroll
        for (int t = 0; t < 4; t++) {
            int ch = c0 + t;
            size_t go = ((size_t)(b * NS + q0g + r)) * ND + hoff + ch * 8;
            uint32_t so = (uint32_t)((r * AT_ROW + ch * 8) * 2);
            cpa16(sb + so,                 (const char*)&g_qh[go]);
            cpa16(sb + 128*AT_ROW*2 + so,  (const char*)&g_ql[go]);
        }
        cpa_commit();
        cpa_wait<0>();
    }
    __syncthreads();

    uint32_t qfh[4][4], qfl[4][4];
    {
        int arow = 16 * wid + (lane & 15);
        int acol = (lane >> 4) * 8;
        #pragma unroll
        for (int s = 0; s < 4; s++) {
            uint32_t ao = (uint32_t)((arow * AT_ROW + s * 16 + acol) * 2);
            ldsm4(qfh[s][0], qfh[s][1], qfh[s][2], qfh[s][3], sb + ao);
            ldsm4(qfl[s][0], qfl[s][1], qfl[s][2], qfl[s][3],
                  sb + 128*AT_ROW*2 + ao);
        }
    }
    __syncthreads();

    // K/V tile loader: keys kt*64..+64, 4 arrays, 2 cpa16 per array per thread
    auto load_kv = [&](int kt, int buf) {
        int r  = tid >> 2;
        int c0 = (tid & 3) * 2;
        uint32_t sbb = sb + buf * A_STAGE;
        #pragma unroll
        for (int t = 0; t < 2; t++) {
            int ch = c0 + t;
            size_t go = ((size_t)(b * NS + kt * 64 + r)) * ND + hoff + ch * 8;
            uint32_t so = (uint32_t)((r * AT_ROW + ch * 8) * 2);
            cpa16(sbb + A_KH + so, (const char*)&g_kh[go]);
            cpa16(sbb + A_KL + so, (const char*)&g_kl[go]);
            cpa16(sbb + A_VH + so, (const char*)&g_vh[go]);
            cpa16(sbb + A_VL + so, (const char*)&g_vl[go]);
        }
    };

    // precomputed lane offsets
    uint32_t kb_off[4][4];   // [kstep s][n-pair np]
    #pragma unroll
    for (int s = 0; s < 4; s++)
        #pragma unroll
        for (int np = 0; np < 4; np++)
            kb_off[s][np] = (uint32_t)(((np * 16 + (g >> 1) * 8 + gi) * AT_ROW
                                        + s * 16 + (g & 1) * 8) * 2);
    uint32_t vb_off[4][4];   // [kstep t][d-pair up]
    #pragma unroll
    for (int t = 0; t < 4; t++)
        #pragma unroll
        for (int up = 0; up < 4; up++)
            vb_off[t][up] = (uint32_t)(((t * 16 + (g & 1) * 8 + gi) * AT_ROW
                                        + (2 * up + (g >> 1)) * 8) * 2);

    float m0r = -1e30f, m1r = -1e30f, l0r = 0.f, l1r = 0.f;
    float accO[8][4];
    #pragma unroll
    for (int dt = 0; dt < 8; dt++)
        #pragma unroll
        for (int e = 0; e < 4; e++) accO[dt][e] = 0.f;

    load_kv(0, 0);
    cpa_commit();

    const int NKT = NS / 64;   // 32
    for (int kt = 0; kt < NKT; kt++) {
        int buf = kt & 1;
        if (kt + 1 < NKT) {
            load_kv(kt + 1, buf ^ 1);
            cpa_commit();
            cpa_wait<1>();
        } else {
            cpa_wait<0>();
        }
        __syncthreads();
        uint32_t kb = sb + buf * A_STAGE;

        // ---- S = Q K^T (hi/lo x3) ----
        float sv[8][4];
        #pragma unroll
        for (int nt = 0; nt < 8; nt++)
            #pragma unroll
            for (int e = 0; e < 4; e++) sv[nt][e] = 0.f;

        #pragma unroll
        for (int s = 0; s < 4; s++) {
            #pragma unroll
            for (int np = 0; np < 4; np++) {
                uint32_t bh0, bh1, bh2, bh3, bl0, bl1, bl2, bl3;
                ldsm4(bh0, bh1, bh2, bh3, kb + A_KH + kb_off[s][np]);
                ldsm4(bl0, bl1, bl2, bl3, kb + A_KL + kb_off[s][np]);
                mma16816(sv[np*2+0], qfh[s], bh0, bh1);
                mma16816(sv[np*2+1], qfh[s], bh2, bh3);
                mma16816(sv[np*2+0], qfh[s], bl0, bl1);
                mma16816(sv[np*2+1], qfh[s], bl2, bl3);
                mma16816(sv[np*2+0], qfl[s], bh0, bh1);
                mma16816(sv[np*2+1], qfl[s], bh2, bh3);
            }
        }

        // ---- online softmax (rows: lane/4 and lane/4+8; quad shares row) ----
        float mt0 = -1e30f, mt1 = -1e30f;
        #pragma unroll
        for (int nt = 0; nt < 8; nt++) {
            mt0 = fmaxf(mt0, fmaxf(sv[nt][0], sv[nt][1]));
            mt1 = fmaxf(mt1, fmaxf(sv[nt][2], sv[nt][3]));
        }
        mt0 = fmaxf(mt0, __shfl_xor_sync(0xffffffffu, mt0, 1));
        mt0 = fmaxf(mt0, __shfl_xor_sync(0xffffffffu, mt0, 2));
        mt1 = fmaxf(mt1, __shfl_xor_sync(0xffffffffu, mt1, 1));
        mt1 = fmaxf(mt1, __shfl_xor_sync(0xffffffffu, mt1, 2));
        float m0n = fmaxf(m0r, mt0), m1n = fmaxf(m1r, mt1);
        float c0 = __expf(m0r - m0n), c1 = __expf(m1r - m1n);
        float ls0 = 0.f, ls1 = 0.f;
        #pragma unroll
        for (int nt = 0; nt < 8; nt++) {
            sv[nt][0] = __expf(sv[nt][0] - m0n);
            sv[nt][1] = __expf(sv[nt][1] - m0n);
            sv[nt][2] = __expf(sv[nt][2] - m1n);
            sv[nt][3] = __expf(sv[nt][3] - m1n);
            ls0 += sv[nt][0] + sv[nt][1];
            ls1 += sv[nt][2] + sv[nt][3];
        }
        ls0 += __shfl_xor_sync(0xffffffffu, ls0, 1);
        ls0 += __shfl_xor_sync(0xffffffffu, ls0, 2);
        ls1 += __shfl_xor_sync(0xffffffffu, ls1, 1);
        ls1 += __shfl_xor_sync(0xffffffffu, ls1, 2);
        l0r = l0r * c0 + ls0;
        l1r = l1r * c1 + ls1;
        m0r = m0n; m1r = m1n;
        #pragma unroll
        for (int dt = 0; dt < 8; dt++) {
            accO[dt][0] *= c0; accO[dt][1] *= c0;
            accO[dt][2] *= c1; accO[dt][3] *= c1;
        }

        // ---- P C-frags -> A-frags (hi/lo), in registers ----
        uint32_t pah[4][4], pal[4][4];
        #pragma unroll
        for (int t = 0; t < 4; t++) {
            split2(sv[2*t  ][0], sv[2*t  ][1], pah[t][0], pal[t][0]);
            split2(sv[2*t  ][2], sv[2*t  ][3], pah[t][1], pal[t][1]);
            split2(sv[2*t+1][0], sv[2*t+1][1], pah[t][2], pal[t][2]);
            split2(sv[2*t+1][2], sv[2*t+1][3], pah[t][3], pal[t][3]);
        }

        // ---- O += P V (hi/lo x3), V via ldmatrix.trans ----
        #pragma unroll
        for (int t = 0; t < 4; t++) {
            #pragma unroll
            for (int up = 0; up < 4; up++) {
                uint32_t vh0, vh1, vh2, vh3, vl0, vl1, vl2, vl3;
                ldsm4t(vh0, vh1, vh2, vh3, kb + A_VH + vb_off[t][up]);
                ldsm4t(vl0, vl1, vl2, vl3, kb + A_VL + vb_off[t][up]);
                mma16816(accO[2*up+0], pah[t], vh0, vh1);
                mma16816(accO[2*up+1], pah[t], vh2, vh3);
                mma16816(accO[2*up+0], pah[t], vl0, vl1);
                mma16816(accO[2*up+1], pah[t], vl2, vl3);
                mma16816(accO[2*up+0], pal[t], vh0, vh1);
                mma16816(accO[2*up+1], pal[t], vh2, vh3);
            }
        }
        __syncthreads();
    }

    // ---- epilogue: normalize, split hi/lo, write for O-projection ----
    float inv0 = 1.f / l0r, inv1 = 1.f / l1r;
    int r0 = q0g + 16 * wid + (lane >> 2);
    int cb = 2 * (lane & 3);
    #pragma unroll
    for (int dt = 0; dt < 8; dt++) {
        int col = dt * 8 + cb;
        float v00 = accO[dt][0] * inv0, v01 = accO[dt][1] * inv0;
        float v10 = accO[dt][2] * inv1, v11 = accO[dt][3] * inv1;
        uint32_t h0, l0, h1, l1;
        split2(v00, v01, h0, l0);
        split2(v10, v11, h1, l1);
        size_t o0 = ((size_t)(b * NS) + r0) * ND + hoff + col;
        size_t o1 = o0 + (size_t)8 * ND;
        *(uint32_t*)&g_ath[o0] = h0;
        *(uint32_t*)&g_atl[o0] = l0;
        *(uint32_t*)&g_ath[o1] = h1;
        *(uint32_t*)&g_atl[o1] = l1;
    }
}

// ---------------------------------------------------------------------------
extern "C" void kernel_launch(void* const* d_in, const int* in_sizes, int n_in,
                              void* d_out, int out_size) {
    const float* x  = (const float*)d_in[0];
    const float* Wq = (const float*)d_in[1];
    const float* bq = (const float*)d_in[2];
    const float* Wk = (const float*)d_in[3];
    const float* bk = (const float*)d_in[4];
    const float* Wv = (const float*)d_in[5];
    const float* bv = (const float*)d_in[6];
    const float* Wo = (const float*)d_in[7];
    const float* bo = (const float*)d_in[8];
    float* out = (float*)d_out;

    __nv_bfloat16 *xh, *xl, *qh, *ql, *kh, *kl, *vh, *vl, *ath, *atl, *wh, *wl;
    cudaGetSymbolAddress((void**)&xh,  g_xh);
    cudaGetSymbolAddress((void**)&xl,  g_xl);
    cudaGetSymbolAddress((void**)&qh,  g_qh);
    cudaGetSymbolAddress((void**)&ql,  g_ql);
    cudaGetSymbolAddress((void**)&kh,  g_kh);
    cudaGetSymbolAddress((void**)&kl,  g_kl);
    cudaGetSymbolAddress((void**)&vh,  g_vh);
    cudaGetSymbolAddress((void**)&vl,  g_vl);
    cudaGetSymbolAddress((void**)&ath, g_ath);
    cudaGetSymbolAddress((void**)&atl, g_atl);
    cudaGetSymbolAddress((void**)&wh,  g_wh);
    cudaGetSymbolAddress((void**)&wl,  g_wl);

    const size_t WSZ = (size_t)ND * ND;

    cudaFuncSetAttribute(tc_gemm_kernel<1>,
                         cudaFuncAttributeMaxDynamicSharedMemorySize, GEMM_SMEM);
    cudaFuncSetAttribute(tc_gemm_kernel<2>,
                         cudaFuncAttributeMaxDynamicSharedMemorySize, GEMM_SMEM);
    cudaFuncSetAttribute(mma_attn_kernel,
                         cudaFuncAttributeMaxDynamicSharedMemorySize, ATT_SMEM);

    // PE + transpose + bf16 split
    pe_split_kernel<<<dim3(NS/32, ND/32, NB), dim3(32, 8)>>>(x);

    // weight splits (Wq folded with 1/sqrt(head_dim) = 0.125)
    wsplit_kernel<<<ND*ND/1024, 256>>>(Wq, wh + 0*WSZ, wl + 0*WSZ, 0.125f);
    wsplit_kernel<<<ND*ND/1024, 256>>>(Wk, wh + 1*WSZ, wl + 1*WSZ, 1.0f);
    wsplit_kernel<<<ND*ND/1024, 256>>>(Wv, wh + 2*WSZ, wl + 2*WSZ, 1.0f);
    wsplit_kernel<<<ND*ND/1024, 256>>>(Wo, wh + 3*WSZ, wl + 3*WSZ, 1.0f);

    // Q/K/V projections (HMMA) -> bf16 hi/lo outputs
    dim3 ggrid(ND/128, NTOK/128);
    tc_gemm_kernel<2><<<ggrid, 256, GEMM_SMEM>>>(xh, xl, wh + 0*WSZ, wl + 0*WSZ,
                                                 bq, 0.125f, nullptr, qh, ql);
    tc_gemm_kernel<2><<<ggrid, 256, GEMM_SMEM>>>(xh, xl, wh + 1*WSZ, wl + 1*WSZ,
                                                 bk, 1.0f, nullptr, kh, kl);
    tc_gemm_kernel<2><<<ggrid, 256, GEMM_SMEM>>>(xh, xl, wh + 2*WSZ, wl + 2*WSZ,
                                                 bv, 1.0f, nullptr, vh, vl);

    // attention (HMMA, hi/lo both GEMMs)
    mma_attn_kernel<<<dim3(NS/128, NH, NB), 256, ATT_SMEM>>>();

    // O-projection with fused [B,D,S] transpose epilogue
    tc_gemm_kernel<1><<<ggrid, 256, GEMM_SMEM>>>(ath, atl, wh + 3*WSZ, wl + 3*WSZ,
                                                 bo, 1.0f, out, nullptr, nullptr);
}